// round 8
// baseline (speedup 1.0000x reference)
#include <cuda_runtime.h>
#include <cuda_bf16.h>
#include <cstdint>
#include <cstring>

// DynamicRouting: grouped 1x1 conv via mma.sync (HMMA bf16, 3-pass fp32 split)
// + fused 3-iter sigmoid routing. con[g][o][p] lives in smem (pad-65 layout).

#define G   8
#define FO  64
#define FI  64
#define HW  4096
#define C   512
#define BSZ 32
#define TP  64
#define NTHREADS 256

#define CPAD 65
#define CONG (FO*CPAD)                 // 4160 floats per group
#define OFF_PD  (G*CONG*4)             // 133120 B
#define OFF_BUF (OFF_PD + 4*G*TP*4)    // +8192 -> 141312 B
#define BUFSZ   32768                  // AHI/ALO/BHI/BLO, 8KB each
#define AHI 0
#define ALO 8192
#define BHI 16384
#define BLO 24576
#define SMEM_TOTAL (OFF_BUF + 2*BUFSZ) // 206848 B

__device__ __forceinline__ uint32_t swz(uint32_t off) {     // XOR row bits[9:7] into [6:4]
    return off ^ ((off >> 3) & 0x70);
}
// split fp32 pair into bf16 hi/lo pairs packed as b32 words
__device__ __forceinline__ void split2(float v0, float v1, uint32_t& hi, uint32_t& lo) {
    __nv_bfloat162 hp = __floats2bfloat162_rn(v0, v1);
    float r0 = v0 - __bfloat162float(hp.x);
    float r1 = v1 - __bfloat162float(hp.y);
    __nv_bfloat162 lp = __floats2bfloat162_rn(r0, r1);
    memcpy(&hi, &hp, 4); memcpy(&lo, &lp, 4);
}
__device__ __forceinline__ void mma16816(float* d,
    uint32_t a0, uint32_t a1, uint32_t a2, uint32_t a3, uint32_t b0, uint32_t b1)
{
    asm volatile("mma.sync.aligned.m16n8k16.row.col.f32.bf16.bf16.f32 "
        "{%0,%1,%2,%3}, {%4,%5,%6,%7}, {%8,%9}, {%0,%1,%2,%3};"
        : "+f"(d[0]), "+f"(d[1]), "+f"(d[2]), "+f"(d[3])
        : "r"(a0), "r"(a1), "r"(a2), "r"(a3), "r"(b0), "r"(b1));
}
__device__ __forceinline__ float sigmoidf(float b) {
    return 1.f / (1.f + __expf(-b));
}

__global__ __launch_bounds__(NTHREADS, 1)
void dynrout_hmma(const float* __restrict__ x, const float* __restrict__ w,
                  const float* __restrict__ bias, float* __restrict__ out)
{
    extern __shared__ char smem[];
    float* con = (float*)smem;
    float* pd  = (float*)(smem + OFF_PD);

    const int tid = threadIdx.x;
    const int wid = tid >> 5, lid = tid & 31;
    const int b   = blockIdx.x >> 6;
    const int p0  = (blockIdx.x & 63) << 6;

    // loader/converter roles
    const int xpx = tid & 63;              // A row (pixel)
    const int xi0 = (tid >> 6) << 4;       // 16 i's per thread
    const int wo  = tid >> 2;              // B row (o)
    const int wi0 = (tid & 3) << 4;

    // mma roles: warp = (m-tile, n-half); lane = (group-of-4, tig)
    const int gr  = lid >> 2, tig = lid & 3;
    const int pb  = (wid & 3) << 4;        // px base of m16 tile
    const int ob  = (wid >> 2) << 5;       // o base of 4 n8-tiles

    const float* xbase = x + (size_t)b * C * HW + p0;

    float xr[16], wr[16];

    auto ldx = [&](int g) {
        const float* xp = xbase + (size_t)g * FI * HW + xpx;
        #pragma unroll
        for (int k = 0; k < 16; k++) xr[k] = __ldg(xp + (size_t)(xi0 + k) * HW);
        const float* wp = w + (size_t)g * FO * FI + wo * FI + wi0;
        #pragma unroll
        for (int k = 0; k < 16; k++) wr[k] = __ldg(wp + k);
    };

    auto cvt = [&](int buf) {
        char* bp = smem + OFF_BUF + buf * BUFSZ;
        uint32_t hi[8], lo[8];
        #pragma unroll
        for (int k = 0; k < 8; k++) split2(xr[2*k], xr[2*k+1], hi[k], lo[k]);
        uint32_t offA = (uint32_t)(xpx * 128 + xi0 * 2);
        *(uint4*)(bp + AHI + swz(offA))    = make_uint4(hi[0], hi[1], hi[2], hi[3]);
        *(uint4*)(bp + AHI + swz(offA+16)) = make_uint4(hi[4], hi[5], hi[6], hi[7]);
        *(uint4*)(bp + ALO + swz(offA))    = make_uint4(lo[0], lo[1], lo[2], lo[3]);
        *(uint4*)(bp + ALO + swz(offA+16)) = make_uint4(lo[4], lo[5], lo[6], lo[7]);
        #pragma unroll
        for (int k = 0; k < 8; k++) split2(wr[2*k], wr[2*k+1], hi[k], lo[k]);
        uint32_t offB = (uint32_t)(wo * 128 + wi0 * 2);
        *(uint4*)(bp + BHI + swz(offB))    = make_uint4(hi[0], hi[1], hi[2], hi[3]);
        *(uint4*)(bp + BHI + swz(offB+16)) = make_uint4(hi[4], hi[5], hi[6], hi[7]);
        *(uint4*)(bp + BLO + swz(offB))    = make_uint4(lo[0], lo[1], lo[2], lo[3]);
        *(uint4*)(bp + BLO + swz(offB+16)) = make_uint4(lo[4], lo[5], lo[6], lo[7]);
    };

    auto mma_group = [&](int g) {
        const char* bp = smem + OFF_BUF + (g & 1) * BUFSZ;
        float acc[4][4];
        #pragma unroll
        for (int j = 0; j < 4; j++)
            #pragma unroll
            for (int k = 0; k < 4; k++) acc[j][k] = 0.f;

        #pragma unroll
        for (int ks = 0; ks < 4; ks++) {
            // A fragments: rows (pb+gr, pb+gr+8), k-words (tig, tig+4) at k-base 8*ks
            uint32_t r0 = (uint32_t)((pb + gr)     * 128 + tig * 4 + ks * 32);
            uint32_t r1 = (uint32_t)((pb + gr + 8) * 128 + tig * 4 + ks * 32);
            uint32_t ah0 = *(const uint32_t*)(bp + AHI + swz(r0));
            uint32_t ah1 = *(const uint32_t*)(bp + AHI + swz(r1));
            uint32_t ah2 = *(const uint32_t*)(bp + AHI + swz(r0 + 16));
            uint32_t ah3 = *(const uint32_t*)(bp + AHI + swz(r1 + 16));
            uint32_t al0 = *(const uint32_t*)(bp + ALO + swz(r0));
            uint32_t al1 = *(const uint32_t*)(bp + ALO + swz(r1));
            uint32_t al2 = *(const uint32_t*)(bp + ALO + swz(r0 + 16));
            uint32_t al3 = *(const uint32_t*)(bp + ALO + swz(r1 + 16));
            #pragma unroll
            for (int jj = 0; jj < 4; jj++) {
                uint32_t rb = (uint32_t)((ob + 8 * jj + gr) * 128 + tig * 4 + ks * 32);
                uint32_t bh0 = *(const uint32_t*)(bp + BHI + swz(rb));
                uint32_t bh1 = *(const uint32_t*)(bp + BHI + swz(rb + 16));
                uint32_t bl0 = *(const uint32_t*)(bp + BLO + swz(rb));
                uint32_t bl1 = *(const uint32_t*)(bp + BLO + swz(rb + 16));
                mma16816(acc[jj], ah0, ah1, ah2, ah3, bh0, bh1);
                mma16816(acc[jj], ah0, ah1, ah2, ah3, bl0, bl1);
                mma16816(acc[jj], al0, al1, al2, al3, bh0, bh1);
            }
        }
        // D frag: d0=(gr, 2tig) d1=(gr, 2tig+1) d2=(gr+8, 2tig) d3=(gr+8, 2tig+1)
        float* cg = con + g * CONG;
        #pragma unroll
        for (int jj = 0; jj < 4; jj++) {
            int o0  = ob + 8 * jj + 2 * tig;
            int px0 = pb + gr;
            cg[(size_t)o0       * CPAD + px0]     = acc[jj][0];
            cg[(size_t)(o0 + 1) * CPAD + px0]     = acc[jj][1];
            cg[(size_t)o0       * CPAD + px0 + 8] = acc[jj][2];
            cg[(size_t)(o0 + 1) * CPAD + px0 + 8] = acc[jj][3];
        }
    };

    // ---------------- pipelined conv ----------------
    ldx(0); cvt(0);
    for (int g = 0; g < G; g++) {
        __syncthreads();                    // converts for g visible; buf[g^1] free
        if (g < G - 1) ldx(g + 1);          // LDG hidden behind MMAs
        mma_group(g);
        if (g < G - 1) cvt((g + 1) & 1);
    }
    __syncthreads();

    // ---------------- routing epilogue (round-6, proven) ----------------
    {
        const int p  = tid & 63;
        const int oq = tid >> 6;
        const int o0 = oq << 4;
        const float* conp = con + p;

        float beta[G];
        #pragma unroll
        for (int g = 0; g < G; g++) beta[g] = 0.f;

        #pragma unroll
        for (int it = 0; it < 2; it++) {
            float al[G], d[G];
            #pragma unroll
            for (int g = 0; g < G; g++) { al[g] = sigmoidf(beta[g]); d[g] = 0.f; }

            #pragma unroll 4
            for (int oo = 0; oo < 16; oo++) {
                const int o = o0 + oo;
                float c[G], vo = 0.f;
                #pragma unroll
                for (int g = 0; g < G; g++) c[g] = conp[g * CONG + o * CPAD];
                #pragma unroll
                for (int g = 0; g < G; g++) vo = fmaf(al[g], c[g], vo);
                #pragma unroll
                for (int g = 0; g < G; g++) d[g] = fmaf(vo, c[g], d[g]);
            }
            #pragma unroll
            for (int g = 0; g < G; g++) pd[(oq * G + g) * TP + p] = d[g];
            __syncthreads();
            #pragma unroll
            for (int g = 0; g < G; g++) {
                float s = 0.f;
                #pragma unroll
                for (int q = 0; q < 4; q++) s += pd[(q * G + g) * TP + p];
                beta[g] += s;
            }
            __syncthreads();
        }

        float al[G];
        #pragma unroll
        for (int g = 0; g < G; g++) al[g] = sigmoidf(beta[g]);

        float* ob2 = out + (size_t)b * FO * HW + p0 + p;
        #pragma unroll 4
        for (int oo = 0; oo < 16; oo++) {
            const int o = o0 + oo;
            float vo = 0.f;
            #pragma unroll
            for (int g = 0; g < G; g++) vo = fmaf(al[g], conp[g * CONG + o * CPAD], vo);
            ob2[(size_t)o * HW] = vo + __ldg(bias + o);
        }
    }
}

extern "C" void kernel_launch(void* const* d_in, const int* in_sizes, int n_in,
                              void* d_out, int out_size)
{
    const float* x    = (const float*)d_in[0];
    const float* wgt  = (const float*)d_in[1];
    const float* bias = (const float*)d_in[2];
    float* out        = (float*)d_out;

    static int attr_set = 0;
    if (!attr_set) {
        cudaFuncSetAttribute(dynrout_hmma,
                             cudaFuncAttributeMaxDynamicSharedMemorySize, SMEM_TOTAL);
        attr_set = 1;
    }
    dim3 grid(BSZ * (HW / TP));   // 2048
    dynrout_hmma<<<grid, NTHREADS, SMEM_TOTAL>>>(x, wgt, bias, out);
}

// round 9
// speedup vs baseline: 1.8237x; 1.8237x over previous
#include <cuda_runtime.h>
#include <cuda_bf16.h>
#include <cstdint>
#include <cstring>

// DynamicRouting: grouped 1x1 conv via mma.sync (HMMA bf16 3-pass fp32 split)
// + fused routing. Weights pre-split to bf16 hi/lo in swizzled B-tile layout
// by a tiny pre-kernel; main kernel cp.asyncs them coalesced.

#define G   8
#define FO  64
#define FI  64
#define HW  4096
#define C   512
#define BSZ 32
#define TP  64
#define NTHREADS 256

#define CPAD 65
#define CONG (FO*CPAD)                 // 4160 floats per group
#define OFF_PD  (G*CONG*4)             // 133120 B
#define OFF_BUF (OFF_PD + 4*G*TP*4)    // 141312 B
#define BUFSZ   32768                  // [AHI 8K | ALO 8K | BHI 8K | BLO 8K]
#define AHI 0
#define ALO 8192
#define BHI 16384
#define BLO 24576
#define SMEM_TOTAL (OFF_BUF + 2*BUFSZ) // 206848 B

// packed weights: per group 16KB = [hi 8KB | lo 8KB], swizzled B-tile layout
__device__ __align__(16) unsigned char g_wpack[G * 16384];

__device__ __forceinline__ uint32_t swz(uint32_t off) {
    return off ^ ((off >> 3) & 0x70);
}
__device__ __forceinline__ uint32_t s2u(const void* p) {
    return (uint32_t)__cvta_generic_to_shared(p);
}
__device__ __forceinline__ void cp16(uint32_t d, const void* s) {
    asm volatile("cp.async.cg.shared.global [%0], [%1], 16;\n" :: "r"(d), "l"(s));
}
__device__ __forceinline__ void cp_commit() {
    asm volatile("cp.async.commit_group;\n");
}
template <int N>
__device__ __forceinline__ void cp_wait() {
    asm volatile("cp.async.wait_group %0;\n" :: "n"(N));
}
__device__ __forceinline__ void split2(float v0, float v1, uint32_t& hi, uint32_t& lo) {
    __nv_bfloat162 hp = __floats2bfloat162_rn(v0, v1);
    float r0 = v0 - __bfloat162float(hp.x);
    float r1 = v1 - __bfloat162float(hp.y);
    __nv_bfloat162 lp = __floats2bfloat162_rn(r0, r1);
    memcpy(&hi, &hp, 4); memcpy(&lo, &lp, 4);
}
__device__ __forceinline__ void mma16816(float* d,
    uint32_t a0, uint32_t a1, uint32_t a2, uint32_t a3, uint32_t b0, uint32_t b1)
{
    asm volatile("mma.sync.aligned.m16n8k16.row.col.f32.bf16.bf16.f32 "
        "{%0,%1,%2,%3}, {%4,%5,%6,%7}, {%8,%9}, {%0,%1,%2,%3};"
        : "+f"(d[0]), "+f"(d[1]), "+f"(d[2]), "+f"(d[3])
        : "r"(a0), "r"(a1), "r"(a2), "r"(a3), "r"(b0), "r"(b1));
}
__device__ __forceinline__ float sigmoidf(float b) {
    return 1.f / (1.f + __expf(-b));
}

// ---- pre-kernel: w fp32 [g][o][i] -> bf16 hi/lo swizzled B tiles ----
__global__ void pack_w_kernel(const float* __restrict__ w) {
    int f = blockIdx.x * blockDim.x + threadIdx.x;   // 0..16383 (word pairs)
    int g = f >> 11, rem = f & 2047;
    int o = rem >> 5, iw = rem & 31;                 // i = 2*iw
    const float* src = w + (((size_t)g * FO + o) * FI + 2 * iw);
    uint32_t hi, lo;
    split2(src[0], src[1], hi, lo);
    uint32_t boff = swz((uint32_t)(o * 128 + iw * 4));
    *(uint32_t*)(g_wpack + g * 16384 + boff)        = hi;
    *(uint32_t*)(g_wpack + g * 16384 + 8192 + boff) = lo;
}

__global__ __launch_bounds__(NTHREADS, 1)
void dynrout_hmma(const float* __restrict__ x, const float* __restrict__ bias,
                  float* __restrict__ out)
{
    extern __shared__ char smem[];
    float* con = (float*)smem;
    float* pd  = (float*)(smem + OFF_PD);

    const int tid = threadIdx.x;
    const int wid = tid >> 5, lid = tid & 31;
    const int b   = blockIdx.x >> 6;
    const int p0  = (blockIdx.x & 63) << 6;

    // A loader/converter roles
    const int xpx = tid & 63;
    const int xi0 = (tid >> 6) << 4;

    // mma roles
    const int gr  = lid >> 2, tig = lid & 3;
    const int pb  = (wid & 3) << 4;
    const int ob  = (wid >> 2) << 5;

    const float* xbase = x + (size_t)b * C * HW + p0;
    float xr[16];

    auto ldx = [&](int g) {
        const float* xp = xbase + (size_t)g * FI * HW + xpx;
        #pragma unroll
        for (int k = 0; k < 16; k++) xr[k] = __ldg(xp + (size_t)(xi0 + k) * HW);
    };

    auto issueB = [&](int g, int buf) {      // 16KB coalesced: hi+lo tiles
        const unsigned char* src = g_wpack + g * 16384;
        uint32_t d0 = s2u(smem + OFF_BUF + buf * BUFSZ + BHI);
        #pragma unroll
        for (int r = 0; r < 4; r++)
            cp16(d0 + (uint32_t)(r * 4096 + tid * 16), src + r * 4096 + tid * 16);
        cp_commit();
    };

    auto cvtA = [&](int buf) {
        char* bp = smem + OFF_BUF + buf * BUFSZ;
        uint32_t hi[8], lo[8];
        #pragma unroll
        for (int k = 0; k < 8; k++) split2(xr[2*k], xr[2*k+1], hi[k], lo[k]);
        uint32_t offA = (uint32_t)(xpx * 128 + xi0 * 2);
        *(uint4*)(bp + AHI + swz(offA))    = make_uint4(hi[0], hi[1], hi[2], hi[3]);
        *(uint4*)(bp + AHI + swz(offA+16)) = make_uint4(hi[4], hi[5], hi[6], hi[7]);
        *(uint4*)(bp + ALO + swz(offA))    = make_uint4(lo[0], lo[1], lo[2], lo[3]);
        *(uint4*)(bp + ALO + swz(offA+16)) = make_uint4(lo[4], lo[5], lo[6], lo[7]);
    };

    auto mma_group = [&](int g) {
        const char* bp = smem + OFF_BUF + (g & 1) * BUFSZ;
        float acc[4][4];
        #pragma unroll
        for (int j = 0; j < 4; j++)
            #pragma unroll
            for (int k = 0; k < 4; k++) acc[j][k] = 0.f;

        #pragma unroll
        for (int ks = 0; ks < 4; ks++) {
            uint32_t r0 = (uint32_t)((pb + gr)     * 128 + tig * 4 + ks * 32);
            uint32_t r1 = (uint32_t)((pb + gr + 8) * 128 + tig * 4 + ks * 32);
            uint32_t ah0 = *(const uint32_t*)(bp + AHI + swz(r0));
            uint32_t ah1 = *(const uint32_t*)(bp + AHI + swz(r1));
            uint32_t ah2 = *(const uint32_t*)(bp + AHI + swz(r0 + 16));
            uint32_t ah3 = *(const uint32_t*)(bp + AHI + swz(r1 + 16));
            uint32_t al0 = *(const uint32_t*)(bp + ALO + swz(r0));
            uint32_t al1 = *(const uint32_t*)(bp + ALO + swz(r1));
            uint32_t al2 = *(const uint32_t*)(bp + ALO + swz(r0 + 16));
            uint32_t al3 = *(const uint32_t*)(bp + ALO + swz(r1 + 16));
            #pragma unroll
            for (int jj = 0; jj < 4; jj++) {
                uint32_t rb = (uint32_t)((ob + 8 * jj + gr) * 128 + tig * 4 + ks * 32);
                uint32_t bh0 = *(const uint32_t*)(bp + BHI + swz(rb));
                uint32_t bh1 = *(const uint32_t*)(bp + BHI + swz(rb + 16));
                uint32_t bl0 = *(const uint32_t*)(bp + BLO + swz(rb));
                uint32_t bl1 = *(const uint32_t*)(bp + BLO + swz(rb + 16));
                mma16816(acc[jj], ah0, ah1, ah2, ah3, bh0, bh1);
                mma16816(acc[jj], ah0, ah1, ah2, ah3, bl0, bl1);
                mma16816(acc[jj], al0, al1, al2, al3, bh0, bh1);
            }
        }
        float* cg = con + g * CONG;
        #pragma unroll
        for (int jj = 0; jj < 4; jj++) {
            int o0  = ob + 8 * jj + 2 * tig;
            int px0 = pb + gr;
            cg[(size_t)o0       * CPAD + px0]     = acc[jj][0];
            cg[(size_t)(o0 + 1) * CPAD + px0]     = acc[jj][1];
            cg[(size_t)o0       * CPAD + px0 + 8] = acc[jj][2];
            cg[(size_t)(o0 + 1) * CPAD + px0 + 8] = acc[jj][3];
        }
    };

    // ---------------- pipelined conv ----------------
    issueB(0, 0);
    ldx(0); cvtA(0);
    for (int g = 0; g < G; g++) {
        if (g < G - 1) { issueB(g + 1, (g + 1) & 1); cp_wait<1>(); }
        else           { cp_wait<0>(); }
        __syncthreads();                 // B(g) + cvtA(g) visible to all warps
        if (g < G - 1) ldx(g + 1);
        mma_group(g);
        if (g < G - 1) cvtA((g + 1) & 1);
    }
    __syncthreads();

    // ---------------- routing epilogue (proven) ----------------
    {
        const int p  = tid & 63;
        const int oq = tid >> 6;
        const int o0 = oq << 4;
        const float* conp = con + p;

        float beta[G];
        #pragma unroll
        for (int g = 0; g < G; g++) beta[g] = 0.f;

        #pragma unroll
        for (int it = 0; it < 2; it++) {
            float al[G], d[G];
            #pragma unroll
            for (int g = 0; g < G; g++) { al[g] = sigmoidf(beta[g]); d[g] = 0.f; }

            #pragma unroll 4
            for (int oo = 0; oo < 16; oo++) {
                const int o = o0 + oo;
                float c[G], vo = 0.f;
                #pragma unroll
                for (int g = 0; g < G; g++) c[g] = conp[g * CONG + o * CPAD];
                #pragma unroll
                for (int g = 0; g < G; g++) vo = fmaf(al[g], c[g], vo);
                #pragma unroll
                for (int g = 0; g < G; g++) d[g] = fmaf(vo, c[g], d[g]);
            }
            #pragma unroll
            for (int g = 0; g < G; g++) pd[(oq * G + g) * TP + p] = d[g];
            __syncthreads();
            #pragma unroll
            for (int g = 0; g < G; g++) {
                float s = 0.f;
                #pragma unroll
                for (int q = 0; q < 4; q++) s += pd[(q * G + g) * TP + p];
                beta[g] += s;
            }
            __syncthreads();
        }

        float al[G];
        #pragma unroll
        for (int g = 0; g < G; g++) al[g] = sigmoidf(beta[g]);

        float* ob2 = out + (size_t)b * FO * HW + p0 + p;
        #pragma unroll 4
        for (int oo = 0; oo < 16; oo++) {
            const int o = o0 + oo;
            float vo = 0.f;
            #pragma unroll
            for (int g = 0; g < G; g++) vo = fmaf(al[g], conp[g * CONG + o * CPAD], vo);
            ob2[(size_t)o * HW] = vo + __ldg(bias + o);
        }
    }
}

extern "C" void kernel_launch(void* const* d_in, const int* in_sizes, int n_in,
                              void* d_out, int out_size)
{
    const float* x    = (const float*)d_in[0];
    const float* wgt  = (const float*)d_in[1];
    const float* bias = (const float*)d_in[2];
    float* out        = (float*)d_out;

    static int attr_set = 0;
    if (!attr_set) {
        cudaFuncSetAttribute(dynrout_hmma,
                             cudaFuncAttributeMaxDynamicSharedMemorySize, SMEM_TOTAL);
        attr_set = 1;
    }

    pack_w_kernel<<<64, 256>>>(wgt);               // 16384 word-pairs
    dim3 grid(BSZ * (HW / TP));                    // 2048
    dynrout_hmma<<<grid, NTHREADS, SMEM_TOTAL>>>(x, bias, out);
}